// round 1
// baseline (speedup 1.0000x reference)
#include <cuda_runtime.h>
#include <cstdint>

#define C_DIM 64
#define F_DIM 128
#define DEG 32
#define MAX_N 20000
#define MAX_E 640000
#define WARPS_PER_CTA 4

// Scratch (device globals: no allocations allowed in kernel_launch)
__device__ float g_wt[F_DIM * C_DIM];   // W^T [f][c], tf32-rounded softmax weights
__device__ int   g_cursor[MAX_N];
__device__ int   g_edge[MAX_E];         // per-node edge lists, DEG per node

// ---------------------------------------------------------------------------
// softmax over the C axis (axis=0) per feature column; store transposed + tf32
// ---------------------------------------------------------------------------
__global__ void softmax_wt_kernel(const float* __restrict__ imp) {
    int f = threadIdx.x;            // 128 threads, one per feature
    float v[C_DIM];
    float m = -3.0e38f;
#pragma unroll
    for (int c = 0; c < C_DIM; c++) { v[c] = imp[c * F_DIM + f]; m = fmaxf(m, v[c]); }
    float s = 0.f;
#pragma unroll
    for (int c = 0; c < C_DIM; c++) { v[c] = expf(v[c] - m); s += v[c]; }
    float inv = 1.0f / s;
#pragma unroll
    for (int c = 0; c < C_DIM; c++) {
        float w = v[c] * inv;
        uint32_t t;
        asm("cvt.rna.tf32.f32 %0, %1;" : "=r"(t) : "f"(w));
        g_wt[f * C_DIM + c] = __uint_as_float(t);
    }
}

__global__ void zero_cursor_kernel(int n) {
    int i = blockIdx.x * blockDim.x + threadIdx.x;
    if (i < n) g_cursor[i] = 0;
}

// Build per-node edge list (every node has exactly DEG=E/N incoming edges)
__global__ void scatter_kernel(const int* __restrict__ dst, int n_edges) {
    int e = blockIdx.x * blockDim.x + threadIdx.x;
    if (e < n_edges) {
        int d = dst[e];
        int slot = atomicAdd(&g_cursor[d], 1);
        if (slot < DEG) g_edge[d * DEG + slot] = e;
    }
}

// ---------------------------------------------------------------------------
// Main fused kernel: one warp = one node.
//   ES[32x128] = CNT_gathered[32x64] @ W[64x128]   (tf32 mma)
//   out[n][f]  = sum_r(ES[r][f] * emb[src[e_r]][f]) / sum_r(ES[r][f])
// ---------------------------------------------------------------------------
__global__ void fogcn_main_kernel(const float* __restrict__ cnt,
                                  const float* __restrict__ emb,
                                  const int*   __restrict__ src,
                                  float*       __restrict__ out,
                                  int n_nodes) {
    extern __shared__ float sm[];
    // layout: s_wt [128][68] | per-warp s_cnt [32][68] | per-warp s_em [32][33]
    float* s_wt  = sm;
    int    wid   = threadIdx.x >> 5;
    float* s_cnt = sm + F_DIM * 68 + wid * (32 * 68);
    float* s_em  = sm + F_DIM * 68 + WARPS_PER_CTA * (32 * 68) + wid * (32 * 33);

    int tid  = threadIdx.x;
    int lane = tid & 31;

    // CTA-cooperative: stage W^T (already tf32) into shared, padded stride 68
    {
        const float4* g = reinterpret_cast<const float4*>(g_wt + tid * C_DIM);
        float* d = s_wt + tid * 68;
#pragma unroll
        for (int j = 0; j < 16; j++) {
            float4 v = g[j];
            d[j * 4 + 0] = v.x; d[j * 4 + 1] = v.y;
            d[j * 4 + 2] = v.z; d[j * 4 + 3] = v.w;
        }
    }
    __syncthreads();

    int node = blockIdx.x * WARPS_PER_CTA + wid;
    if (node >= n_nodes) return;

    // lane r owns edge-row r of this node
    int e    = g_edge[node * DEG + lane];
    int srow = src[e];

    // gather this edge's cnt row -> shared A tile (tf32-rounded)
    {
        const float4* p = reinterpret_cast<const float4*>(cnt + (size_t)e * C_DIM);
        float* d = s_cnt + lane * 68;
#pragma unroll
        for (int j = 0; j < 16; j++) {
            float4 v = p[j];
            uint32_t t0, t1, t2, t3;
            asm("cvt.rna.tf32.f32 %0, %1;" : "=r"(t0) : "f"(v.x));
            asm("cvt.rna.tf32.f32 %0, %1;" : "=r"(t1) : "f"(v.y));
            asm("cvt.rna.tf32.f32 %0, %1;" : "=r"(t2) : "f"(v.z));
            asm("cvt.rna.tf32.f32 %0, %1;" : "=r"(t3) : "f"(v.w));
            d[j * 4 + 0] = __uint_as_float(t0);
            d[j * 4 + 1] = __uint_as_float(t1);
            d[j * 4 + 2] = __uint_as_float(t2);
            d[j * 4 + 3] = __uint_as_float(t3);
        }
    }
    __syncwarp();

    const float* embrow = emb + (size_t)srow * F_DIM;
    float*       orow   = out + (size_t)node * F_DIM;
    int gid = lane >> 2;     // row-group 0..7
    int tig = lane & 3;      // thread-in-group 0..3

    // Process the 128 output features in 4 chunks of 32 columns
    for (int cb = 0; cb < F_DIM; cb += 32) {
        float acc[2][4][4];
#pragma unroll
        for (int mt = 0; mt < 2; mt++)
#pragma unroll
            for (int t = 0; t < 4; t++)
#pragma unroll
                for (int i = 0; i < 4; i++) acc[mt][t][i] = 0.f;

#pragma unroll
        for (int ks = 0; ks < 8; ks++) {
            int kc = ks * 8 + tig;
            uint32_t a[2][4], b[4][2];
#pragma unroll
            for (int mt = 0; mt < 2; mt++) {
                int r = mt * 16 + gid;
                a[mt][0] = __float_as_uint(s_cnt[r * 68 + kc]);
                a[mt][1] = __float_as_uint(s_cnt[(r + 8) * 68 + kc]);
                a[mt][2] = __float_as_uint(s_cnt[r * 68 + kc + 4]);
                a[mt][3] = __float_as_uint(s_cnt[(r + 8) * 68 + kc + 4]);
            }
#pragma unroll
            for (int t = 0; t < 4; t++) {
                int n = cb + t * 8 + gid;
                b[t][0] = __float_as_uint(s_wt[n * 68 + kc]);
                b[t][1] = __float_as_uint(s_wt[n * 68 + kc + 4]);
            }
#pragma unroll
            for (int mt = 0; mt < 2; mt++)
#pragma unroll
                for (int t = 0; t < 4; t++)
                    asm volatile(
                        "mma.sync.aligned.m16n8k8.row.col.f32.tf32.tf32.f32 "
                        "{%0,%1,%2,%3}, {%4,%5,%6,%7}, {%8,%9}, {%0,%1,%2,%3};"
                        : "+f"(acc[mt][t][0]), "+f"(acc[mt][t][1]),
                          "+f"(acc[mt][t][2]), "+f"(acc[mt][t][3])
                        : "r"(a[mt][0]), "r"(a[mt][1]), "r"(a[mt][2]), "r"(a[mt][3]),
                          "r"(b[t][0]), "r"(b[t][1]));
        }

        // stage this warp's embedding chunk [32 rows][32 cols] (coalesced 128B/row)
        __syncwarp();
        {
            const float4* p = reinterpret_cast<const float4*>(embrow + cb);
            float* d = s_em + lane * 33;
#pragma unroll
            for (int j = 0; j < 8; j++) {
                float4 v = p[j];
                d[j * 4 + 0] = v.x; d[j * 4 + 1] = v.y;
                d[j * 4 + 2] = v.z; d[j * 4 + 3] = v.w;
            }
        }
        __syncwarp();

        // fused epilogue: column-sum of ES and ES*EM over the 32 edge-rows
#pragma unroll
        for (int t = 0; t < 4; t++) {
            int lc = t * 8 + tig * 2;
            float em00 = s_em[gid * 33 + lc],        em01 = s_em[gid * 33 + lc + 1];
            float em10 = s_em[(gid + 8) * 33 + lc],  em11 = s_em[(gid + 8) * 33 + lc + 1];
            float em20 = s_em[(gid + 16) * 33 + lc], em21 = s_em[(gid + 16) * 33 + lc + 1];
            float em30 = s_em[(gid + 24) * 33 + lc], em31 = s_em[(gid + 24) * 33 + lc + 1];

            float num0 = acc[0][t][0] * em00 + acc[0][t][2] * em10
                       + acc[1][t][0] * em20 + acc[1][t][2] * em30;
            float num1 = acc[0][t][1] * em01 + acc[0][t][3] * em11
                       + acc[1][t][1] * em21 + acc[1][t][3] * em31;
            float den0 = acc[0][t][0] + acc[0][t][2] + acc[1][t][0] + acc[1][t][2];
            float den1 = acc[0][t][1] + acc[0][t][3] + acc[1][t][1] + acc[1][t][3];
#pragma unroll
            for (int off = 4; off < 32; off <<= 1) {
                num0 += __shfl_xor_sync(0xffffffffu, num0, off);
                num1 += __shfl_xor_sync(0xffffffffu, num1, off);
                den0 += __shfl_xor_sync(0xffffffffu, den0, off);
                den1 += __shfl_xor_sync(0xffffffffu, den1, off);
            }
            if (lane < 4) {
                orow[cb + lc]     = num0 / den0;
                orow[cb + lc + 1] = num1 / den1;
            }
        }
    }
}

// ---------------------------------------------------------------------------
extern "C" void kernel_launch(void* const* d_in, const int* in_sizes, int n_in,
                              void* d_out, int out_size) {
    const float* cnt = (const float*)d_in[0];
    const float* emb = (const float*)d_in[1];
    const float* imp = (const float*)d_in[2];
    const int*   src = (const int*)d_in[3];
    const int*   dst = (const int*)d_in[4];
    float*       out = (float*)d_out;

    int n_edges = in_sizes[3];
    int n_nodes = in_sizes[1] / F_DIM;
    if (n_edges > MAX_E) n_edges = MAX_E;
    if (n_nodes > MAX_N) n_nodes = MAX_N;

    softmax_wt_kernel<<<1, F_DIM>>>(imp);
    zero_cursor_kernel<<<(n_nodes + 255) / 256, 256>>>(n_nodes);
    scatter_kernel<<<(n_edges + 255) / 256, 256>>>(dst, n_edges);

    int smem_bytes = (F_DIM * 68 + WARPS_PER_CTA * (32 * 68) + WARPS_PER_CTA * (32 * 33))
                     * (int)sizeof(float);   // 86528 B
    cudaFuncSetAttribute(fogcn_main_kernel,
                         cudaFuncAttributeMaxDynamicSharedMemorySize, smem_bytes);

    int nblocks = (n_nodes + WARPS_PER_CTA - 1) / WARPS_PER_CTA;
    fogcn_main_kernel<<<nblocks, 32 * WARPS_PER_CTA, smem_bytes>>>(cnt, emb, src, out, n_nodes);
}

// round 2
// speedup vs baseline: 1.6624x; 1.6624x over previous
#include <cuda_runtime.h>
#include <cstdint>

#define C_DIM 64
#define F_DIM 128
#define DEG 32
#define MAX_N 20000
#define MAX_E 640000
#define WARPS_PER_CTA 6

// stride (in floats) of rows in shared
#define WT_STRIDE 80     // s_wt rows (permuted W^T), conflict-free LDS.128
#define CNT_STRIDE 68    // s_cnt rows, conflict-free LDS.32 frag loads
#define ES_STRIDE 40     // s_es rows (reuses s_cnt region), conflict-free

// per-warp shared block: s_cnt (reused as s_es) + s_src
#define WARP_SM_WORDS (32 * CNT_STRIDE + 32)   // 2208 words = 8832 B
#define WT_WORDS (F_DIM * WT_STRIDE)           // 10240 words = 40960 B

// Scratch (device globals: no allocations allowed in kernel_launch)
__device__ float g_wt[F_DIM * C_DIM];   // permuted W^T [f][perm(c)], tf32
__device__ int   g_cursor[MAX_N];
__device__ int   g_edge[MAX_E];         // per-node edge lists, DEG per node

// column permutation within 16-col groups so (kc, kc+4) pairs of adjacent
// k-steps become one contiguous float4:  pos = 4*(local&3) + (local>>2)
__device__ __forceinline__ int perm64(int c) {
    int local = c & 15;
    return (c & ~15) | (4 * (local & 3) + (local >> 2));
}

// ---------------------------------------------------------------------------
// softmax over C axis per feature column; store transposed + permuted + tf32
// ---------------------------------------------------------------------------
__global__ void softmax_wt_kernel(const float* __restrict__ imp) {
    int f = threadIdx.x;            // 128 threads, one per feature
    float v[C_DIM];
    float m = -3.0e38f;
#pragma unroll
    for (int c = 0; c < C_DIM; c++) { v[c] = imp[c * F_DIM + f]; m = fmaxf(m, v[c]); }
    float s = 0.f;
#pragma unroll
    for (int c = 0; c < C_DIM; c++) { v[c] = expf(v[c] - m); s += v[c]; }
    float inv = 1.0f / s;
#pragma unroll
    for (int c = 0; c < C_DIM; c++) {
        float w = v[c] * inv;
        uint32_t t;
        asm("cvt.rna.tf32.f32 %0, %1;" : "=r"(t) : "f"(w));
        g_wt[f * C_DIM + perm64(c)] = __uint_as_float(t);
    }
}

__global__ void zero_cursor_kernel(int n) {
    int i = blockIdx.x * blockDim.x + threadIdx.x;
    if (i < n) g_cursor[i] = 0;
}

__global__ void scatter_kernel(const int* __restrict__ dst, int n_edges) {
    int e = blockIdx.x * blockDim.x + threadIdx.x;
    if (e < n_edges) {
        int d = dst[e];
        int slot = atomicAdd(&g_cursor[d], 1);
        if (slot < DEG) g_edge[d * DEG + slot] = e;
    }
}

// ---------------------------------------------------------------------------
// Main fused kernel: one warp = one node.
// ---------------------------------------------------------------------------
__global__ void __launch_bounds__(32 * WARPS_PER_CTA, 2)
fogcn_main_kernel(const float* __restrict__ cnt,
                  const float* __restrict__ emb,
                  const int*   __restrict__ src,
                  float*       __restrict__ out,
                  int n_nodes) {
    extern __shared__ float sm[];
    float* s_wt  = sm;                                  // [128][80] permuted
    int    wid   = threadIdx.x >> 5;
    float* s_cnt = sm + WT_WORDS + wid * WARP_SM_WORDS; // [32][68], later s_es
    int*   s_src = (int*)(s_cnt + 32 * CNT_STRIDE);     // [32]

    int tid  = threadIdx.x;
    int lane = tid & 31;

    // CTA-cooperative: stage permuted W^T into shared (stride 80)
    for (int row = tid >> 4; row < F_DIM; row += (blockDim.x >> 4)) {
        int u = tid & 15;   // 16 float4 per 64-word row
        float4 v = reinterpret_cast<const float4*>(g_wt + row * C_DIM)[u];
        float* d = s_wt + row * WT_STRIDE + u * 4;
        d[0] = v.x; d[1] = v.y; d[2] = v.z; d[3] = v.w;
    }
    __syncthreads();

    int node = blockIdx.x * WARPS_PER_CTA + wid;
    if (node >= n_nodes) return;

    // lane r owns edge-row r of this node
    int e    = g_edge[node * DEG + lane];
    int srow = src[e];
    s_src[lane] = srow;

    // --- cooperative, coalesced cnt gather: 16 lanes per 256B row ---
    {
        int half = lane >> 4;       // which of 2 rows this instr
        int u    = lane & 15;       // 16B chunk within row
#pragma unroll 4
        for (int j = 0; j < 16; j++) {
            int row = 2 * j + half;
            int er  = __shfl_sync(0xffffffffu, e, row);
            float4 v = reinterpret_cast<const float4*>(cnt + (size_t)er * C_DIM)[u];
            uint32_t t0, t1, t2, t3;
            asm("cvt.rna.tf32.f32 %0, %1;" : "=r"(t0) : "f"(v.x));
            asm("cvt.rna.tf32.f32 %0, %1;" : "=r"(t1) : "f"(v.y));
            asm("cvt.rna.tf32.f32 %0, %1;" : "=r"(t2) : "f"(v.z));
            asm("cvt.rna.tf32.f32 %0, %1;" : "=r"(t3) : "f"(v.w));
            float* d = s_cnt + row * CNT_STRIDE + u * 4;
            d[0] = __uint_as_float(t0); d[1] = __uint_as_float(t1);
            d[2] = __uint_as_float(t2); d[3] = __uint_as_float(t3);
        }
    }
    __syncwarp();

    int gid = lane >> 2;     // row-group 0..7
    int tig = lane & 3;      // thread-in-group 0..3

    // --- hoist all A fragments into registers (chunk-independent) ---
    uint32_t af[8][2][4];    // [kstep][mt][frag]
#pragma unroll
    for (int ks = 0; ks < 8; ks++) {
        int kc = ks * 8 + tig;
#pragma unroll
        for (int mt = 0; mt < 2; mt++) {
            int r = mt * 16 + gid;
            af[ks][mt][0] = __float_as_uint(s_cnt[r * CNT_STRIDE + kc]);
            af[ks][mt][1] = __float_as_uint(s_cnt[(r + 8) * CNT_STRIDE + kc]);
            af[ks][mt][2] = __float_as_uint(s_cnt[r * CNT_STRIDE + kc + 4]);
            af[ks][mt][3] = __float_as_uint(s_cnt[(r + 8) * CNT_STRIDE + kc + 4]);
        }
    }
    __syncwarp();            // s_cnt now dead -> reuse as s_es

    float* s_es = s_cnt;     // [32][40]
    const float* embc = emb + lane;   // lane owns chunk-column `lane`
    float* orow = out + (size_t)node * F_DIM;

#pragma unroll 1
    for (int cb = 0; cb < F_DIM; cb += 32) {
        float acc[2][4][4];
#pragma unroll
        for (int mt = 0; mt < 2; mt++)
#pragma unroll
            for (int t = 0; t < 4; t++)
#pragma unroll
                for (int i = 0; i < 4; i++) acc[mt][t][i] = 0.f;

#pragma unroll
        for (int d = 0; d < 4; d++) {
            // one float4 per t: B pairs for ksteps 2d and 2d+1 (permuted layout)
            float4 b4[4];
#pragma unroll
            for (int t = 0; t < 4; t++) {
                int n = cb + t * 8 + gid;
                b4[t] = *reinterpret_cast<const float4*>(
                            s_wt + n * WT_STRIDE + d * 16 + 4 * tig);
            }
#pragma unroll
            for (int sub = 0; sub < 2; sub++) {
                int ks = 2 * d + sub;
#pragma unroll
                for (int t = 0; t < 4; t++) {
                    uint32_t b0 = __float_as_uint(sub ? b4[t].z : b4[t].x);
                    uint32_t b1 = __float_as_uint(sub ? b4[t].w : b4[t].y);
#pragma unroll
                    for (int mt = 0; mt < 2; mt++)
                        asm volatile(
                            "mma.sync.aligned.m16n8k8.row.col.f32.tf32.tf32.f32 "
                            "{%0,%1,%2,%3}, {%4,%5,%6,%7}, {%8,%9}, {%0,%1,%2,%3};"
                            : "+f"(acc[mt][t][0]), "+f"(acc[mt][t][1]),
                              "+f"(acc[mt][t][2]), "+f"(acc[mt][t][3])
                            : "r"(af[ks][mt][0]), "r"(af[ks][mt][1]),
                              "r"(af[ks][mt][2]), "r"(af[ks][mt][3]),
                              "r"(b0), "r"(b1));
                }
            }
        }

        // --- write ES fragments to shared (stride 40, conflict-free) ---
        __syncwarp();
#pragma unroll
        for (int mt = 0; mt < 2; mt++)
#pragma unroll
            for (int t = 0; t < 4; t++) {
                int r = mt * 16 + gid;
                int c = t * 8 + tig * 2;
                *reinterpret_cast<float2*>(s_es + r * ES_STRIDE + c) =
                    make_float2(acc[mt][t][0], acc[mt][t][1]);
                *reinterpret_cast<float2*>(s_es + (r + 8) * ES_STRIDE + c) =
                    make_float2(acc[mt][t][2], acc[mt][t][3]);
            }
        __syncwarp();

        // --- reduction: lane = chunk-feature; loop edge rows; coalesced emb ---
        float num = 0.f, den = 0.f;
#pragma unroll 4
        for (int r = 0; r < 32; r++) {
            float es = s_es[r * ES_STRIDE + lane];
            float ev = embc[(size_t)s_src[r] * F_DIM + cb];
            num = fmaf(es, ev, num);
            den += es;
        }
        orow[cb + lane] = num / den;
        __syncwarp();   // protect s_es before next chunk's stores
    }
}

// ---------------------------------------------------------------------------
extern "C" void kernel_launch(void* const* d_in, const int* in_sizes, int n_in,
                              void* d_out, int out_size) {
    const float* cnt = (const float*)d_in[0];
    const float* emb = (const float*)d_in[1];
    const float* imp = (const float*)d_in[2];
    const int*   src = (const int*)d_in[3];
    const int*   dst = (const int*)d_in[4];
    float*       out = (float*)d_out;

    int n_edges = in_sizes[3];
    int n_nodes = in_sizes[1] / F_DIM;
    if (n_edges > MAX_E) n_edges = MAX_E;
    if (n_nodes > MAX_N) n_nodes = MAX_N;

    softmax_wt_kernel<<<1, F_DIM>>>(imp);
    zero_cursor_kernel<<<(n_nodes + 255) / 256, 256>>>(n_nodes);
    scatter_kernel<<<(n_edges + 255) / 256, 256>>>(dst, n_edges);

    int smem_bytes = (WT_WORDS + WARPS_PER_CTA * WARP_SM_WORDS) * (int)sizeof(float);
    cudaFuncSetAttribute(fogcn_main_kernel,
                         cudaFuncAttributeMaxDynamicSharedMemorySize, smem_bytes);

    int nblocks = (n_nodes + WARPS_PER_CTA - 1) / WARPS_PER_CTA;
    fogcn_main_kernel<<<nblocks, 32 * WARPS_PER_CTA, smem_bytes>>>(cnt, emb, src, out, n_nodes);
}